// round 1
// baseline (speedup 1.0000x reference)
#include <cuda_runtime.h>

// Problem constants
#define B_SZ   8
#define MCC    10
#define INC    16
#define OUTC   32
#define HW_IN  128
#define HW_OUT 64
#define KTOT   144          // 3*3*16
#define NTOT   320          // MC*OUTC

// Tile config
#define M_TILE 128          // 2 output rows x 64 cols
#define N_TILE 64
#define THREADS 128

// smem: As[144][128] floats, then union( Bs[144][64], Xraw[16][5][128] )
#define AS_FLOATS   (KTOT * M_TILE)              // 18432
#define UNION_FLOATS 10240                        // max(144*64=9216, 16*5*128=10240)
#define SMEM_FLOATS (AS_FLOATS + UNION_FLOATS)    // 28672
#define SMEM_BYTES  (SMEM_FLOATS * 4)             // 114688

__device__ float d_W[KTOT * NTOT];   // [k][n], n = mc*32 + oc

// ---------- f32x2 helpers ----------
__device__ __forceinline__ double dup2(float x) {
    double d;
    asm("mov.b64 %0, {%1, %1};" : "=d"(d) : "f"(x));
    return d;
}
__device__ __forceinline__ void fma2(double &acc, double a, double b) {
    asm("fma.rn.f32x2 %0, %1, %2, %0;" : "+d"(acc) : "d"(a), "d"(b));
}
__device__ __forceinline__ void unpack2(double d, float &lo, float &hi) {
    asm("mov.b64 {%0, %1}, %2;" : "=f"(lo), "=f"(hi) : "d"(d));
}

__device__ __forceinline__ void fast_sincos(float v, float &s, float &c) {
    // reduce to [-pi, pi] (2-step Cody-Waite), then MUFU sin/cos
    float t = rintf(v * 0.15915494309189535f);
    float r = fmaf(t, -6.2831855f, v);          // hi(2pi) = 0x40C90FDB
    r = fmaf(t, 1.7484555e-7f, r);              // -lo(2pi)
    s = __sinf(r);
    c = __cosf(r);
}

// ---------- weight materialization: W[k][mc*32+oc] ----------
__global__ void prep_w_kernel(const float* __restrict__ mean,
                              const float* __restrict__ ls,
                              const float* __restrict__ eps) {
    int i = blockIdx.x * 256 + threadIdx.x;     // i over [mc][d][oc] = 46080
    if (i >= MCC * KTOT * OUTC) return;
    int oc = i & 31;
    int t  = i >> 5;
    int d  = t % KTOT;
    int mc = t / KTOT;
    float w = fmaf(eps[i], expf(0.5f * ls[d * OUTC + oc]), mean[d * OUTC + oc]);
    d_W[d * NTOT + mc * OUTC + oc] = w;
}

// ---------- main conv + RFF kernel ----------
__global__ void __launch_bounds__(THREADS, 2)
conv_rff_kernel(const float* __restrict__ x,
                const float* __restrict__ theta,
                float* __restrict__ out) {
    extern __shared__ float sm[];
    float* As = sm;                    // [144][128]
    float* Bs = sm + AS_FLOATS;        // [144][64]   (after raw phase)
    float* Xr = sm + AS_FLOATS;        // [16][5][128] raw x patch (overlaps Bs)

    const int tid   = threadIdx.x;
    const int ntile = blockIdx.x;      // 0..4   (64-channel slab)
    const int rg    = blockIdx.y;      // 0..31  (output-row pair)
    const int b     = blockIdx.z;      // 0..7

    // ---- 1) stage raw x rows: iy = 4*rg - 1 + r, r=0..4 ----
    {
        const float* xb = x + (size_t)b * INC * HW_IN * HW_IN;
        const int iy0 = 4 * rg - 1;
        for (int i = tid; i < INC * 5 * HW_IN; i += THREADS) {
            int ix = i & 127;
            int t2 = i >> 7;           // 0..79
            int r  = t2 % 5;
            int c  = t2 / 5;
            int iy = iy0 + r;
            float v = 0.f;
            if ((unsigned)iy < (unsigned)HW_IN) v = xb[(c * HW_IN + iy) * HW_IN + ix];
            Xr[(c * 5 + r) * HW_IN + ix] = v;
        }
    }
    __syncthreads();

    // ---- 2) build im2col A: A[k][m], m = tid; k = kh*48 + kw*16 + c ----
    {
        const int oyp = tid >> 6;      // 0..1
        const int ox  = tid & 63;
        #pragma unroll 4
        for (int k = 0; k < KTOT; ++k) {
            int kh  = k / 48;
            int rem = k - kh * 48;
            int kw  = rem >> 4;
            int c   = rem & 15;
            int r   = 2 * oyp + kh;            // 0..4
            int ix  = 2 * ox + kw - 1;         // -1..127
            float v = 0.f;
            if (ix >= 0) v = Xr[(c * 5 + r) * HW_IN + ix];
            As[k * M_TILE + tid] = v;
        }
    }
    __syncthreads();

    // ---- 3) load weight slab B[k][0..63] (overwrites Xr) ----
    {
        const float* Wg = d_W + ntile * N_TILE;
        for (int i = tid; i < KTOT * N_TILE; i += THREADS) {
            int k = i >> 6;
            int n = i & 63;
            Bs[k * N_TILE + n] = Wg[k * NTOT + n];
        }
    }
    __syncthreads();

    // ---- 4) mainloop: frag 8m x 8n, f32x2-packed along m ----
    const int ng = tid & 7;
    const int mg = tid >> 3;
    const float* Ap = As + mg * 8;
    const float* Bp = Bs + ng * 8;

    double acc[8][4];
    #pragma unroll
    for (int j = 0; j < 8; ++j)
        #pragma unroll
        for (int i = 0; i < 4; ++i)
            acc[j][i] = 0.0;

    #pragma unroll 6
    for (int k = 0; k < KTOT; ++k) {
        double2 a01 = *reinterpret_cast<const double2*>(Ap);
        double2 a23 = *reinterpret_cast<const double2*>(Ap + 4);
        float4 b0 = *reinterpret_cast<const float4*>(Bp);
        float4 b1 = *reinterpret_cast<const float4*>(Bp + 4);
        float bv[8] = {b0.x, b0.y, b0.z, b0.w, b1.x, b1.y, b1.z, b1.w};
        #pragma unroll
        for (int j = 0; j < 8; ++j) {
            double bd = dup2(bv[j]);
            fma2(acc[j][0], a01.x, bd);
            fma2(acc[j][1], a01.y, bd);
            fma2(acc[j][2], a23.x, bd);
            fma2(acc[j][3], a23.y, bd);
        }
        Ap += M_TILE;
        Bp += N_TILE;
    }

    // ---- 5) epilogue: scale * {cos, sin}, vectorized stores ----
    const float scale = expf(0.5f * theta[0]) * 0.0027621358640644f; // 1/sqrt(32*64*64)
    const int oy  = rg * 2 + (mg >> 3);
    const int oxb = (mg & 7) * 8;

    #pragma unroll
    for (int j = 0; j < 8; ++j) {
        int ngl = ntile * N_TILE + ng * 8 + j;     // global channel in [0,320)
        int mc  = ngl >> 5;
        int oc  = ngl & 31;
        float* pc = out + (((size_t)(b * (MCC * 2 * OUTC) + mc * 64 + oc)) * HW_OUT + oy) * HW_OUT + oxb;
        float* ps = pc + (size_t)OUTC * HW_OUT * HW_OUT;   // +32 channels

        float cs[8], sn[8];
        #pragma unroll
        for (int i = 0; i < 4; ++i) {
            float v0, v1;
            unpack2(acc[j][i], v0, v1);
            float s0, c0, s1, c1;
            fast_sincos(v0, s0, c0);
            fast_sincos(v1, s1, c1);
            cs[2*i]   = scale * c0;  cs[2*i+1] = scale * c1;
            sn[2*i]   = scale * s0;  sn[2*i+1] = scale * s1;
        }
        *reinterpret_cast<float4*>(pc)     = make_float4(cs[0], cs[1], cs[2], cs[3]);
        *reinterpret_cast<float4*>(pc + 4) = make_float4(cs[4], cs[5], cs[6], cs[7]);
        *reinterpret_cast<float4*>(ps)     = make_float4(sn[0], sn[1], sn[2], sn[3]);
        *reinterpret_cast<float4*>(ps + 4) = make_float4(sn[4], sn[5], sn[6], sn[7]);
    }
}

extern "C" void kernel_launch(void* const* d_in, const int* in_sizes, int n_in,
                              void* d_out, int out_size) {
    const float* x     = (const float*)d_in[0];
    const float* theta = (const float*)d_in[1];
    const float* mean  = (const float*)d_in[2];
    const float* ls    = (const float*)d_in[3];
    const float* eps   = (const float*)d_in[4];
    float* out = (float*)d_out;

    prep_w_kernel<<<(MCC * KTOT * OUTC + 255) / 256, 256>>>(mean, ls, eps);

    cudaFuncSetAttribute(conv_rff_kernel,
                         cudaFuncAttributeMaxDynamicSharedMemorySize, SMEM_BYTES);
    dim3 grid(5, 32, 8);   // n-slab, row-pair, batch
    conv_rff_kernel<<<grid, THREADS, SMEM_BYTES>>>(x, theta, out);
}

// round 2
// speedup vs baseline: 1.4695x; 1.4695x over previous
#include <cuda_runtime.h>

// Problem constants
#define MCC    10
#define INC    16
#define OUTC   32
#define HW_IN  128
#define HW_OUT 64
#define KTOT   144          // 3*3*16
#define NTOT   320          // MC*OUTC

// Tile config
#define THREADS 256
#define N_TILE  64
#define XROWS   9           // input rows per CTA (4 output rows, stride 2, k=3)
#define PR      128         // floats per (c,row): even[0..63] | odd[64..127]

#define XS_FLOATS   (INC * XROWS * PR)      // 18432
#define BS_FLOATS   (KTOT * N_TILE)         // 9216
#define SMEM_FLOATS (XS_FLOATS + BS_FLOATS) // 27648
#define SMEM_BYTES  (SMEM_FLOATS * 4)       // 110592 -> 2 CTAs/SM

__device__ float d_W[KTOT * NTOT];   // [k][n], n = mc*32 + oc

// ---------- f32x2 helpers ----------
__device__ __forceinline__ double dup2(float x) {
    double d;
    asm("mov.b64 %0, {%1, %1};" : "=d"(d) : "f"(x));
    return d;
}
__device__ __forceinline__ double pack2(float lo, float hi) {
    double d;
    asm("mov.b64 %0, {%1, %2};" : "=d"(d) : "f"(lo), "f"(hi));
    return d;
}
__device__ __forceinline__ void fma2(double &acc, double a, double b) {
    asm("fma.rn.f32x2 %0, %1, %2, %0;" : "+d"(acc) : "d"(a), "d"(b));
}
__device__ __forceinline__ void unpack2(double d, float &lo, float &hi) {
    asm("mov.b64 {%0, %1}, %2;" : "=f"(lo), "=f"(hi) : "d"(d));
}

__device__ __forceinline__ void fast_sincos(float v, float &s, float &c) {
    float t = rintf(v * 0.15915494309189535f);
    float r = fmaf(t, -6.2831855f, v);
    r = fmaf(t, 1.7484555e-7f, r);
    s = __sinf(r);
    c = __cosf(r);
}

// ---------- weight materialization: W[k][mc*32+oc] ----------
__global__ void prep_w_kernel(const float* __restrict__ mean,
                              const float* __restrict__ ls,
                              const float* __restrict__ eps) {
    int i = blockIdx.x * 256 + threadIdx.x;     // i over [mc][d][oc] = 46080
    if (i >= MCC * KTOT * OUTC) return;
    int oc = i & 31;
    int t  = i >> 5;
    int d  = t % KTOT;
    int mc = t / KTOT;
    float w = fmaf(eps[i], expf(0.5f * ls[d * OUTC + oc]), mean[d * OUTC + oc]);
    d_W[d * NTOT + mc * OUTC + oc] = w;
}

// ---------- main conv + RFF kernel ----------
__global__ void __launch_bounds__(THREADS, 2)
conv_rff_kernel(const float* __restrict__ x,
                const float* __restrict__ theta,
                float* __restrict__ out) {
    extern __shared__ float sm[];
    float* Xs = sm;                 // [16][9][128] parity-split raw patch
    float* Bs = sm + XS_FLOATS;     // [144][64] weight slab

    const int tid   = threadIdx.x;
    const int ntile = blockIdx.x;   // 0..4   (64-channel slab)
    const int rg    = blockIdx.y;   // 0..15  (4 output rows each)
    const int b     = blockIdx.z;   // 0..7

    // ---- 1) stage raw x rows parity-split: iy = 8*rg - 1 + r, r=0..8 ----
    {
        const float* xb = x + (size_t)b * INC * HW_IN * HW_IN;
        const int iy0 = 8 * rg - 1;
        for (int i = tid; i < INC * XROWS * HW_IN; i += THREADS) {
            int ix = i & 127;
            int t2 = i >> 7;           // 0..143
            int r  = t2 % XROWS;
            int c  = t2 / XROWS;
            int iy = iy0 + r;
            float v = 0.f;
            if ((unsigned)iy < (unsigned)HW_IN) v = xb[(c * HW_IN + iy) * HW_IN + ix];
            Xs[(c * XROWS + r) * PR + (ix & 1) * 64 + (ix >> 1)] = v;
        }
    }

    // ---- 2) stage weight slab B[k][0..63] (vectorized) ----
    {
        const float* Wg = d_W + ntile * N_TILE;
        for (int i = tid; i < (KTOT * N_TILE) / 4; i += THREADS) {
            int k  = i >> 4;
            int n4 = (i & 15) * 4;
            float4 v = *reinterpret_cast<const float4*>(Wg + k * NTOT + n4);
            *reinterpret_cast<float4*>(Bs + k * N_TILE + n4) = v;
        }
    }
    __syncthreads();

    // ---- 3) mainloop: frag 8m x 8n, f32x2-packed along m ----
    const int ng  = tid & 7;          // n-group: 8 channels
    const int mg  = tid >> 3;         // m-group: 8 pixels
    const int oyp = mg >> 3;          // 0..3 (output row within tile)
    const int ox0 = (mg & 7) * 8;     // 0..56

    double acc[8][4];
    #pragma unroll
    for (int j = 0; j < 8; ++j)
        #pragma unroll
        for (int i = 0; i < 4; ++i)
            acc[j][i] = 0.0;

    for (int kh = 0; kh < 3; ++kh) {
        #pragma unroll 2
        for (int c = 0; c < INC; ++c) {
            const float* row  = Xs + (c * XROWS + 2 * oyp + kh) * PR;
            const float* orow = row + 64;
            double2 e01 = *reinterpret_cast<const double2*>(row + ox0);
            double2 e23 = *reinterpret_cast<const double2*>(row + ox0 + 4);
            double2 q01 = *reinterpret_cast<const double2*>(orow + ox0);
            double2 q23 = *reinterpret_cast<const double2*>(orow + ox0 + 4);
            float om1 = ox0 ? orow[ox0 - 1] : 0.f;   // ix = -1 pad

            float o0,o1,o2,o3,o4,o5,o6;
            { float hi; unpack2(q01.x, o0, o1); unpack2(q01.y, o2, o3);
              unpack2(q23.x, o4, o5); unpack2(q23.y, o6, hi); (void)hi; }

            double p[3][4];
            p[0][0] = pack2(om1, o0); p[0][1] = pack2(o1, o2);
            p[0][2] = pack2(o3, o4);  p[0][3] = pack2(o5, o6);
            p[1][0] = e01.x; p[1][1] = e01.y; p[1][2] = e23.x; p[1][3] = e23.y;
            p[2][0] = q01.x; p[2][1] = q01.y; p[2][2] = q23.x; p[2][3] = q23.y;

            #pragma unroll
            for (int kw = 0; kw < 3; ++kw) {
                const float* bp = Bs + (kh * 48 + kw * 16 + c) * N_TILE + ng * 8;
                float4 b0 = *reinterpret_cast<const float4*>(bp);
                float4 b1 = *reinterpret_cast<const float4*>(bp + 4);
                float bv[8] = {b0.x, b0.y, b0.z, b0.w, b1.x, b1.y, b1.z, b1.w};
                #pragma unroll
                for (int j = 0; j < 8; ++j) {
                    double bd = dup2(bv[j]);
                    fma2(acc[j][0], p[kw][0], bd);
                    fma2(acc[j][1], p[kw][1], bd);
                    fma2(acc[j][2], p[kw][2], bd);
                    fma2(acc[j][3], p[kw][3], bd);
                }
            }
        }
    }

    // ---- 4) epilogue: scale * {cos, sin}, vectorized stores ----
    const float scale = expf(0.5f * theta[0]) * 0.0027621358640644f; // 1/sqrt(32*64*64)
    const int oy = rg * 4 + oyp;

    #pragma unroll
    for (int j = 0; j < 8; ++j) {
        int ngl = ntile * N_TILE + ng * 8 + j;     // global channel in [0,320)
        int mc  = ngl >> 5;
        int oc  = ngl & 31;
        float* pc = out + (((size_t)(b * (MCC * 2 * OUTC) + mc * 64 + oc)) * HW_OUT + oy) * HW_OUT + ox0;
        float* ps = pc + (size_t)OUTC * HW_OUT * HW_OUT;   // sin block (+32 channels)

        float cs[8], sn[8];
        #pragma unroll
        for (int i = 0; i < 4; ++i) {
            float v0, v1;
            unpack2(acc[j][i], v0, v1);
            float s0, c0, s1, c1;
            fast_sincos(v0, s0, c0);
            fast_sincos(v1, s1, c1);
            cs[2*i]   = scale * c0;  cs[2*i+1] = scale * c1;
            sn[2*i]   = scale * s0;  sn[2*i+1] = scale * s1;
        }
        *reinterpret_cast<float4*>(pc)     = make_float4(cs[0], cs[1], cs[2], cs[3]);
        *reinterpret_cast<float4*>(pc + 4) = make_float4(cs[4], cs[5], cs[6], cs[7]);
        *reinterpret_cast<float4*>(ps)     = make_float4(sn[0], sn[1], sn[2], sn[3]);
        *reinterpret_cast<float4*>(ps + 4) = make_float4(sn[4], sn[5], sn[6], sn[7]);
    }
}

extern "C" void kernel_launch(void* const* d_in, const int* in_sizes, int n_in,
                              void* d_out, int out_size) {
    const float* x     = (const float*)d_in[0];
    const float* theta = (const float*)d_in[1];
    const float* mean  = (const float*)d_in[2];
    const float* ls    = (const float*)d_in[3];
    const float* eps   = (const float*)d_in[4];
    float* out = (float*)d_out;

    prep_w_kernel<<<(MCC * KTOT * OUTC + 255) / 256, 256>>>(mean, ls, eps);

    cudaFuncSetAttribute(conv_rff_kernel,
                         cudaFuncAttributeMaxDynamicSharedMemorySize, SMEM_BYTES);
    dim3 grid(5, 16, 8);   // n-slab, row-quad, batch
    conv_rff_kernel<<<grid, THREADS, SMEM_BYTES>>>(x, theta, out);
}